// round 13
// baseline (speedup 1.0000x reference)
#include <cuda_runtime.h>
#include <math.h>

// ---------------------------------------------------------------------------
// MinkUNet block, round 13: round-12 base (595.9us) + time-MLP folded into
// stats(H0) launch, r1+yds merged into one launch, conv0 chunk loop made
// compile-time (KC0=25) with unroll-5 for load batching.
// ---------------------------------------------------------------------------

#define MAXN 131072
#define MAXM 131072
#define MAXB 64
#define SB   256     // stats partial blocks (fixed -> deterministic)

__device__ __align__(16) float dH0 [MAXN*32];   // conv0 raw
__device__ __align__(16) float dR1 [MAXN*16];   // h@Wb1 raw
__device__ __align__(16) float dR2 [MAXN*16];   // conv3 raw
__device__ __align__(16) float dY3 [MAXN*64];   // r@Wb3 raw
__device__ __align__(16) float dYDS[MAXN*64];   // h@Wds raw
__device__ __align__(16) float dH2 [MAXN*64];   // residual out
__device__ __align__(16) float dORAW[MAXM*64];  // conv2 raw
__device__ __align__(16) float dT  [MAXB*32];   // time mlp out
__device__ float dPA[SB*128];                   // partials [block][2C]
__device__ float dPB[SB*128];
__device__ float dSC[6][64];                    // per-BN scale
__device__ float dSH[6][64];                    // per-BN shift

// ---------------- packed f32x2 helpers (sm_100a) ----------------
__device__ __forceinline__ unsigned long long ffma2(unsigned long long a,
                                                    unsigned long long b,
                                                    unsigned long long c) {
    unsigned long long d;
    asm("fma.rn.f32x2 %0, %1, %2, %3;" : "=l"(d) : "l"(a), "l"(b), "l"(c));
    return d;
}
__device__ __forceinline__ unsigned long long bcast2(float x) {
    unsigned long long d;
    unsigned int u = __float_as_uint(x);
    asm("mov.b64 %0, {%1, %1};" : "=l"(d) : "r"(u));
    return d;
}

// ---------------------------------------------------------------- stats
__device__ __forceinline__ void stats_body(const float4* __restrict__ src,
                                           int n4, int C, float* __restrict__ part,
                                           int bid, float* sh) {
    int t = threadIdx.x;
    int gid = bid*256 + t;
    float s0=0,s1=0,s2=0,s3=0,q0=0,q1=0,q2=0,q3=0;
    for (int i = gid; i < n4; i += SB*256) {
        float4 v = src[i];
        s0+=v.x; q0+=v.x*v.x; s1+=v.y; q1+=v.y*v.y;
        s2+=v.z; q2+=v.z*v.z; s3+=v.w; q3+=v.w*v.w;
    }
    sh[t*8+0]=s0; sh[t*8+1]=s1; sh[t*8+2]=s2; sh[t*8+3]=s3;
    sh[t*8+4]=q0; sh[t*8+5]=q1; sh[t*8+6]=q2; sh[t*8+7]=q3;
    __syncthreads();
    if (t < C) {              // channel of (tt,j) is (4*tt+j)%C
        int j = t & 3, t0 = t >> 2, step = C >> 2;
        float S = 0.f, Q = 0.f;
        for (int tt = t0; tt < 256; tt += step) { S += sh[tt*8+j]; Q += sh[tt*8+4+j]; }
        part[bid*2*C + t]     = S;
        part[bid*2*C + C + t] = Q;
    }
}

__global__ void k_stats(const float4* __restrict__ src, int n4, int C,
                        float* __restrict__ part) {
    __shared__ float sh[256*8];
    stats_body(src, n4, C, part, blockIdx.x, sh);
}

// stats(H0) + time-MLP in one launch: blocks [0,SB) = stats, block SB = time.
__global__ void k_stats_time(const float4* __restrict__ src, int n4, int C,
                             float* __restrict__ part,
                             const float* __restrict__ emb,
                             const float* __restrict__ Wt1, const float* __restrict__ bt1,
                             const float* __restrict__ Wt2, const float* __restrict__ bt2,
                             const int*   __restrict__ time, int B) {
    __shared__ float sh[256*8];
    if (blockIdx.x < SB) { stats_body(src, n4, C, part, blockIdx.x, sh); return; }
    // time MLP block
    int t = threadIdx.x;
    int nt = B*32;
    float* z = sh;
    if (t < nt) {
        int b = t >> 5, c = t & 31;
        const float* e = emb + time[b]*32;
        float v = bt1[c];
        #pragma unroll
        for (int j = 0; j < 32; j++) v += e[j]*Wt1[j*32+c];
        v = v / (1.f + expf(-v));              // silu
        z[t] = v;
    }
    __syncthreads();
    if (t < nt) {
        int b = t >> 5, c = t & 31;
        float o = bt2[c];
        #pragma unroll
        for (int j = 0; j < 32; j++) o += z[b*32+j]*Wt2[j*32+c];
        dT[t] = o;
    }
}

// two stats in one launch: blocks [0,SB) -> src1 (C=16 -> dPA),
// blocks [SB,2SB) -> src2 (C=64 -> dPB)
__global__ void k_stats2(const float4* __restrict__ src1, int n41,
                         const float4* __restrict__ src2, int n42) {
    __shared__ float sh[256*8];
    if (blockIdx.x < SB) stats_body(src1, n41, 16, dPA, blockIdx.x, sh);
    else                 stats_body(src2, n42, 64, dPB, blockIdx.x - SB, sh);
}

// ---------------------------------------------------------------- finalize
__device__ __forceinline__ void fin_body(const float* __restrict__ part, int C,
                                         int rows, const float* __restrict__ g,
                                         const float* __restrict__ b, int slot,
                                         float* red) {
    int t = threadIdx.x, C2 = 2*C;
    if (t < C2*8) {
        int sub = t / C2, e = t - sub*C2;
        float s = 0.f;
        for (int i = sub; i < SB; i += 8) s += part[i*C2 + e];
        red[sub*C2 + e] = s;
    }
    __syncthreads();
    if (t < C) {
        float S = 0.f, SS = 0.f;
        #pragma unroll
        for (int k = 0; k < 8; k++) { S += red[k*C2 + t]; SS += red[k*C2 + C + t]; }
        float inv  = 1.f / (float)rows;
        float mean = S * inv;
        float var  = SS * inv - mean*mean;
        float sc   = g[t] * rsqrtf(var + 1e-5f);
        dSC[slot][t] = sc;
        dSH[slot][t] = b[t] - mean*sc;
    }
}

__global__ void k_fin(const float* __restrict__ part, int C, int rows,
                      const float* __restrict__ g, const float* __restrict__ b,
                      int slot) {
    __shared__ float red[8*128];
    fin_body(part, C, rows, g, b, slot, red);
}

__global__ void k_fin2(int rows,
                       const float* __restrict__ g1, const float* __restrict__ b1,
                       const float* __restrict__ g4, const float* __restrict__ b4) {
    __shared__ float red[8*128];
    if (blockIdx.x == 0) fin_body(dPA, 16, rows, g1, b1, 1, red);
    else                 fin_body(dPB, 64, rows, g4, b4, 4, red);
}

// ------------------------------------- conv k=5 (dense, packed f32x2)
// KC0=25: 125 = 5*25, chunk loop bound is compile-time -> unroll for MLP.
#define KC0 25
__global__ void __launch_bounds__(256) k_conv0(const float* __restrict__ x,
                        const int* __restrict__ nb5,
                        const float* __restrict__ W0, int N) {
    __shared__ float4 sW[KC0*64];              // 25 KiB
    int row = blockIdx.x*256 + threadIdx.x;
    unsigned long long acc[16];                // 32 ch as 16 pairs
    #pragma unroll
    for (int c = 0; c < 16; c++) acc[c] = 0ull;

    #pragma unroll 1
    for (int k0 = 0; k0 < 125; k0 += KC0) {
        const float4* srcw = (const float4*)(W0 + k0*256);
        for (int i = threadIdx.x; i < KC0*64; i += 256) sW[i] = srcw[i];
        __syncthreads();
        if (row < N) {
            const int* nbp = nb5 + (size_t)k0*N + row;
            #pragma unroll 5
            for (int kk = 0; kk < KC0; kk++) {
                int idx = nbp[(size_t)kk*N];
                if (idx < N) {
                    const float4* xr = (const float4*)(x + (size_t)idx*8);
                    float4 a = xr[0], bb = xr[1];
                    float xv[8] = {a.x,a.y,a.z,a.w,bb.x,bb.y,bb.z,bb.w};
                    const ulonglong2* wk = (const ulonglong2*)(sW + kk*64);
                    #pragma unroll
                    for (int j = 0; j < 8; j++) {
                        unsigned long long xj = bcast2(xv[j]);
                        #pragma unroll
                        for (int c = 0; c < 8; c++) {
                            ulonglong2 w = wk[j*8 + c];
                            acc[c*2+0] = ffma2(xj, w.x, acc[c*2+0]);
                            acc[c*2+1] = ffma2(xj, w.y, acc[c*2+1]);
                        }
                    }
                }
            }
        }
        __syncthreads();
    }
    if (row < N) {
        ulonglong2* o = (ulonglong2*)(dH0 + (size_t)row*32);
        #pragma unroll
        for (int q = 0; q < 8; q++) {
            ulonglong2 v; v.x = acc[q*2]; v.y = acc[q*2+1];
            o[q] = v;
        }
    }
}

// ----------------- merged R1 + YDS (one launch, block-range split) -----------
__global__ void __launch_bounds__(256) k_r1yds(const float* __restrict__ Wb1,
                      const float* __restrict__ Wds,
                      const int* __restrict__ bidx, int N, int nbHalf) {
    __shared__ float4 sW[64*16];               // 16 KiB (r1 uses first 4 KiB)
    __shared__ float ssc[32], ssh[32];
    bool isR1 = blockIdx.x < nbHalf;
    if (isR1) {
        if (threadIdx.x < 256) sW[threadIdx.x] = ((const float4*)Wb1)[threadIdx.x];
    } else {
        for (int i = threadIdx.x; i < 64*16; i += 256) sW[i] = ((const float4*)Wds)[i];
    }
    if (threadIdx.x < 32) { ssc[threadIdx.x] = dSC[0][threadIdx.x];
                            ssh[threadIdx.x] = dSH[0][threadIdx.x]; }
    __syncthreads();

    if (isR1) {
        int row = blockIdx.x*256 + threadIdx.x;
        if (row >= N) return;
        unsigned long long acc[8];
        #pragma unroll
        for (int c = 0; c < 8; c++) acc[c] = 0ull;
        const ulonglong2* wk2 = (const ulonglong2*)sW;
        const float4* h4 = (const float4*)(dH0 + (size_t)row*32);
        #pragma unroll
        for (int q = 0; q < 8; q++) {
            float4 vv = h4[q];
            float hv[4] = {vv.x,vv.y,vv.z,vv.w};
            #pragma unroll
            for (int u = 0; u < 4; u++) {
                int j = q*4+u;
                float hj = fmaxf(ssc[j]*hv[u] + ssh[j], 0.f);
                unsigned long long xj = bcast2(hj);
                #pragma unroll
                for (int c4 = 0; c4 < 4; c4++) {
                    ulonglong2 w = wk2[j*4+c4];
                    acc[c4*2+0] = ffma2(xj, w.x, acc[c4*2+0]);
                    acc[c4*2+1] = ffma2(xj, w.y, acc[c4*2+1]);
                }
            }
        }
        const float4* t4 = (const float4*)(dT + (size_t)bidx[row]*32);
        #pragma unroll
        for (int q = 0; q < 8; q++) {
            float4 vv = t4[q];
            float hv[4] = {vv.x,vv.y,vv.z,vv.w};
            #pragma unroll
            for (int u = 0; u < 4; u++) {
                int j = 32 + q*4+u;
                unsigned long long xj = bcast2(hv[u]);
                #pragma unroll
                for (int c4 = 0; c4 < 4; c4++) {
                    ulonglong2 w = wk2[j*4+c4];
                    acc[c4*2+0] = ffma2(xj, w.x, acc[c4*2+0]);
                    acc[c4*2+1] = ffma2(xj, w.y, acc[c4*2+1]);
                }
            }
        }
        ulonglong2* o = (ulonglong2*)(dR1 + (size_t)row*16);
        #pragma unroll
        for (int q = 0; q < 4; q++) {
            ulonglong2 v; v.x = acc[q*2]; v.y = acc[q*2+1];
            o[q] = v;
        }
    } else {
        int row = (blockIdx.x - nbHalf)*256 + threadIdx.x;
        if (row >= N) return;
        unsigned long long acc[32];
        #pragma unroll
        for (int c = 0; c < 32; c++) acc[c] = 0ull;
        const ulonglong2* wk2 = (const ulonglong2*)sW;
        const float4* h4 = (const float4*)(dH0 + (size_t)row*32);
        #pragma unroll
        for (int q = 0; q < 8; q++) {
            float4 vv = h4[q];
            float hv[4] = {vv.x,vv.y,vv.z,vv.w};
            #pragma unroll
            for (int u = 0; u < 4; u++) {
                int j = q*4+u;
                float hj = fmaxf(ssc[j]*hv[u] + ssh[j], 0.f);
                unsigned long long xj = bcast2(hj);
                #pragma unroll
                for (int c4 = 0; c4 < 16; c4++) {
                    ulonglong2 w = wk2[j*16+c4];
                    acc[c4*2+0] = ffma2(xj, w.x, acc[c4*2+0]);
                    acc[c4*2+1] = ffma2(xj, w.y, acc[c4*2+1]);
                }
            }
        }
        const float4* t4 = (const float4*)(dT + (size_t)bidx[row]*32);
        #pragma unroll
        for (int q = 0; q < 8; q++) {
            float4 vv = t4[q];
            float hv[4] = {vv.x,vv.y,vv.z,vv.w};
            #pragma unroll
            for (int u = 0; u < 4; u++) {
                int j = 32 + q*4+u;
                unsigned long long xj = bcast2(hv[u]);
                #pragma unroll
                for (int c4 = 0; c4 < 16; c4++) {
                    ulonglong2 w = wk2[j*16+c4];
                    acc[c4*2+0] = ffma2(xj, w.x, acc[c4*2+0]);
                    acc[c4*2+1] = ffma2(xj, w.y, acc[c4*2+1]);
                }
            }
        }
        ulonglong2* o = (ulonglong2*)(dYDS + (size_t)row*64);
        #pragma unroll
        for (int q = 0; q < 16; q++) {
            ulonglong2 v; v.x = acc[q*2]; v.y = acc[q*2+1];
            o[q] = v;
        }
    }
}

// ------------------------------------- conv k=3 (dense, packed f32x2)
__global__ void __launch_bounds__(256) k_conv3(const int* __restrict__ nb3,
                        const float* __restrict__ Wb2, int N) {
    __shared__ float4 sW[27*64];               // 27 KiB
    __shared__ float ssc[16], ssh[16];
    for (int i = threadIdx.x; i < 27*64; i += 256) sW[i] = ((const float4*)Wb2)[i];
    if (threadIdx.x < 16) { ssc[threadIdx.x] = dSC[1][threadIdx.x];
                            ssh[threadIdx.x] = dSH[1][threadIdx.x]; }
    __syncthreads();
    int row = blockIdx.x*256 + threadIdx.x;
    if (row >= N) return;

    unsigned long long acc[8];                 // 16 ch as 8 pairs
    #pragma unroll
    for (int c = 0; c < 8; c++) acc[c] = 0ull;

    #pragma unroll 3
    for (int k = 0; k < 27; k++) {
        int idx = nb3[(size_t)k*N + row];
        if (idx < N) {
            const float4* rp = (const float4*)(dR1 + (size_t)idx*16);
            const ulonglong2* wk = (const ulonglong2*)(sW + k*64);
            #pragma unroll
            for (int q = 0; q < 4; q++) {
                float4 vv = rp[q];
                float av[4] = {vv.x,vv.y,vv.z,vv.w};
                #pragma unroll
                for (int u = 0; u < 4; u++) {
                    int j = q*4+u;
                    float aj = fmaxf(ssc[j]*av[u] + ssh[j], 0.f);
                    unsigned long long xj = bcast2(aj);
                    #pragma unroll
                    for (int c4 = 0; c4 < 4; c4++) {
                        ulonglong2 w = wk[j*4+c4];
                        acc[c4*2+0] = ffma2(xj, w.x, acc[c4*2+0]);
                        acc[c4*2+1] = ffma2(xj, w.y, acc[c4*2+1]);
                    }
                }
            }
        }
    }
    ulonglong2* o = (ulonglong2*)(dR2 + (size_t)row*16);
    #pragma unroll
    for (int q = 0; q < 4; q++) {
        ulonglong2 v; v.x = acc[q*2]; v.y = acc[q*2+1];
        o[q] = v;
    }
}

// ---------------------------------------------------- Y3 = bnrelu(R2) @ Wb3
__global__ void __launch_bounds__(256,2) k_y3(const float* __restrict__ Wb3, int N) {
    __shared__ float4 sW[16*16];               // 16x64
    __shared__ float ssc[16], ssh[16];
    if (threadIdx.x < 256) sW[threadIdx.x] = ((const float4*)Wb3)[threadIdx.x];
    if (threadIdx.x < 16) { ssc[threadIdx.x] = dSC[2][threadIdx.x];
                            ssh[threadIdx.x] = dSH[2][threadIdx.x]; }
    __syncthreads();
    int row = blockIdx.x*256 + threadIdx.x;
    if (row >= N) return;

    unsigned long long acc[32];                // 64 ch as 32 pairs
    #pragma unroll
    for (int c = 0; c < 32; c++) acc[c] = 0ull;

    const ulonglong2* wk2 = (const ulonglong2*)sW;
    const float4* rp = (const float4*)(dR2 + (size_t)row*16);
    #pragma unroll
    for (int q = 0; q < 4; q++) {
        float4 vv = rp[q];
        float av[4] = {vv.x,vv.y,vv.z,vv.w};
        #pragma unroll
        for (int u = 0; u < 4; u++) {
            int j = q*4+u;
            float aj = fmaxf(ssc[j]*av[u] + ssh[j], 0.f);
            unsigned long long xj = bcast2(aj);
            #pragma unroll
            for (int c4 = 0; c4 < 16; c4++) {
                ulonglong2 w = wk2[j*16+c4];
                acc[c4*2+0] = ffma2(xj, w.x, acc[c4*2+0]);
                acc[c4*2+1] = ffma2(xj, w.y, acc[c4*2+1]);
            }
        }
    }
    ulonglong2* o = (ulonglong2*)(dY3 + (size_t)row*64);
    #pragma unroll
    for (int q = 0; q < 16; q++) {
        ulonglong2 v; v.x = acc[q*2]; v.y = acc[q*2+1];
        o[q] = v;
    }
}

// -------------------------------------- H2 = relu(bn3(Y3) + bnds(YDS))
__global__ void k_h2(int N) {
    int i = blockIdx.x*256 + threadIdx.x;
    int total4 = N*16;
    if (i >= total4) return;
    int c0 = (i*4) & 63;
    float4 y  = ((const float4*)dY3 )[i];
    float4 yd = ((const float4*)dYDS)[i];
    float4 r;
    r.x = fmaxf(dSC[3][c0+0]*y.x + dSH[3][c0+0] + dSC[4][c0+0]*yd.x + dSH[4][c0+0], 0.f);
    r.y = fmaxf(dSC[3][c0+1]*y.y + dSH[3][c0+1] + dSC[4][c0+1]*yd.y + dSH[4][c0+1], 0.f);
    r.z = fmaxf(dSC[3][c0+2]*y.z + dSH[3][c0+2] + dSC[4][c0+2]*yd.z + dSH[4][c0+2], 0.f);
    r.w = fmaxf(dSC[3][c0+3]*y.w + dSH[3][c0+3] + dSC[4][c0+3]*yd.w + dSH[4][c0+3], 0.f);
    ((float4*)dH2)[i] = r;
}

// ------------------------------------- conv k=2 (dense, packed f32x2)
#define KC2 2
__global__ void __launch_bounds__(256,2) k_conv2(const int* __restrict__ nb2,
                        const float* __restrict__ Wd, int M, int N) {
    __shared__ float4 sW[KC2*1024];            // 32 KiB
    int row = blockIdx.x*256 + threadIdx.x;
    unsigned long long acc[32];                // 64 ch as 32 pairs
    #pragma unroll
    for (int c = 0; c < 32; c++) acc[c] = 0ull;

    for (int k0 = 0; k0 < 8; k0 += KC2) {
        const float4* srcw = (const float4*)(Wd + k0*4096);
        for (int i = threadIdx.x; i < KC2*1024; i += 256) sW[i] = srcw[i];
        __syncthreads();
        if (row < M) {
            #pragma unroll
            for (int kk = 0; kk < KC2; kk++) {
                int idx = nb2[(size_t)(k0+kk)*M + row];
                if (idx < N) {
                    const float4* hp = (const float4*)(dH2 + (size_t)idx*64);
                    const ulonglong2* wk = (const ulonglong2*)(sW + kk*1024);
                    #pragma unroll
                    for (int q = 0; q < 16; q++) {
                        float4 h4 = hp[q];
                        float hv[4] = {h4.x,h4.y,h4.z,h4.w};
                        #pragma unroll
                        for (int u = 0; u < 4; u++) {
                            int j = q*4+u;
                            unsigned long long xj = bcast2(hv[u]);
                            const ulonglong2* wj = wk + j*16;
                            #pragma unroll
                            for (int c4 = 0; c4 < 16; c4++) {
                                ulonglong2 w = wj[c4];
                                acc[c4*2+0] = ffma2(xj, w.x, acc[c4*2+0]);
                                acc[c4*2+1] = ffma2(xj, w.y, acc[c4*2+1]);
                            }
                        }
                    }
                }
            }
        }
        __syncthreads();
    }
    if (row < M) {
        ulonglong2* o = (ulonglong2*)(dORAW + (size_t)row*64);
        #pragma unroll
        for (int q = 0; q < 16; q++) {
            ulonglong2 v; v.x = acc[q*2]; v.y = acc[q*2+1];
            o[q] = v;
        }
    }
}

// ---------------------------------------------------- out = relu(bn(ORAW))
__global__ void k_apply(float* __restrict__ out, int M) {
    int i = blockIdx.x*256 + threadIdx.x;
    int total4 = M*16;
    if (i >= total4) return;
    int c0 = (i*4) & 63;
    float4 v = ((const float4*)dORAW)[i];
    float4 r;
    r.x = fmaxf(dSC[5][c0+0]*v.x + dSH[5][c0+0], 0.f);
    r.y = fmaxf(dSC[5][c0+1]*v.y + dSH[5][c0+1], 0.f);
    r.z = fmaxf(dSC[5][c0+2]*v.z + dSH[5][c0+2], 0.f);
    r.w = fmaxf(dSC[5][c0+3]*v.w + dSH[5][c0+3], 0.f);
    ((float4*)out)[i] = r;
}

// ---------------------------------------------------------------------------
extern "C" void kernel_launch(void* const* d_in, const int* in_sizes, int n_in,
                              void* d_out, int out_size) {
    const float* x      = (const float*)d_in[0];
    const float* W0     = (const float*)d_in[1];
    const float* g0     = (const float*)d_in[2];
    const float* b0     = (const float*)d_in[3];
    const float* emb    = (const float*)d_in[4];
    const float* Wt1    = (const float*)d_in[5];
    const float* bt1    = (const float*)d_in[6];
    const float* Wt2    = (const float*)d_in[7];
    const float* bt2    = (const float*)d_in[8];
    const float* Wb1    = (const float*)d_in[9];
    const float* gb1    = (const float*)d_in[10];
    const float* bb1    = (const float*)d_in[11];
    const float* Wb2    = (const float*)d_in[12];
    const float* gb2    = (const float*)d_in[13];
    const float* bb2    = (const float*)d_in[14];
    const float* Wb3    = (const float*)d_in[15];
    const float* gb3    = (const float*)d_in[16];
    const float* bb3    = (const float*)d_in[17];
    const float* Wds    = (const float*)d_in[18];
    const float* gds    = (const float*)d_in[19];
    const float* bds    = (const float*)d_in[20];
    const float* Wd     = (const float*)d_in[21];
    const float* gd     = (const float*)d_in[22];
    const float* bd     = (const float*)d_in[23];
    const int*   time   = (const int*)  d_in[24];
    const int*   bidx   = (const int*)  d_in[25];
    const int*   nb5    = (const int*)  d_in[26];
    const int*   nb3    = (const int*)  d_in[27];
    const int*   nb2    = (const int*)  d_in[28];
    float* out = (float*)d_out;

    int N = in_sizes[0] / 8;
    int B = in_sizes[24];
    int M = in_sizes[28] / 8;

    int nb = (N + 255) / 256;
    int mb = (M + 255) / 256;

    float4 *pH0, *pR1, *pR2, *pY3, *pYDS, *pOR;
    float *pA, *pB;
    cudaGetSymbolAddress((void**)&pH0, dH0);
    cudaGetSymbolAddress((void**)&pR1, dR1);
    cudaGetSymbolAddress((void**)&pR2, dR2);
    cudaGetSymbolAddress((void**)&pY3, dY3);
    cudaGetSymbolAddress((void**)&pYDS, dYDS);
    cudaGetSymbolAddress((void**)&pOR, dORAW);
    cudaGetSymbolAddress((void**)&pA, dPA);
    cudaGetSymbolAddress((void**)&pB, dPB);

    k_conv0<<<nb, 256>>>(x, nb5, W0, N);
    k_stats_time<<<SB+1, 256>>>(pH0, N*8, 32, pA,
                                emb, Wt1, bt1, Wt2, bt2, time, B);
    k_fin<<<1, 1024>>>(pA, 32, N, g0, b0, 0);

    k_r1yds<<<2*nb, 256>>>(Wb1, Wds, bidx, N, nb);
    k_stats2<<<2*SB, 256>>>(pR1, N*4, pYDS, N*16);
    k_fin2<<<2, 1024>>>(N, gb1, bb1, gds, bds);

    k_conv3<<<nb, 256>>>(nb3, Wb2, N);
    k_stats<<<SB, 256>>>(pR2, N*4, 16, pA);
    k_fin<<<1, 1024>>>(pA, 16, N, gb2, bb2, 2);

    k_y3<<<nb, 256>>>(Wb3, N);
    k_stats<<<SB, 256>>>(pY3, N*16, 64, pA);
    k_fin<<<1, 1024>>>(pA, 64, N, gb3, bb3, 3);

    k_h2<<<(N*16 + 255)/256, 256>>>(N);

    k_conv2<<<mb, 256>>>(nb2, Wd, M, N);
    k_stats<<<SB, 256>>>(pOR, M*16, 64, pA);
    k_fin<<<1, 1024>>>(pA, 64, M, gd, bd, 5);

    k_apply<<<(M*16 + 255)/256, 256>>>(out, M);
}

// round 14
// speedup vs baseline: 1.0341x; 1.0341x over previous
#include <cuda_runtime.h>
#include <math.h>

// ---------------------------------------------------------------------------
// MinkUNet block, round 14: round-12 verbatim (595.9us best) with ONE change:
// k_conv0 __launch_bounds__(256,3) to lift register-limited occupancy.
// ---------------------------------------------------------------------------

#define MAXN 131072
#define MAXM 131072
#define MAXB 64
#define SB   256     // stats partial blocks (fixed -> deterministic)

__device__ __align__(16) float dH0 [MAXN*32];   // conv0 raw
__device__ __align__(16) float dR1 [MAXN*16];   // h@Wb1 raw
__device__ __align__(16) float dR2 [MAXN*16];   // conv3 raw
__device__ __align__(16) float dY3 [MAXN*64];   // r@Wb3 raw
__device__ __align__(16) float dYDS[MAXN*64];   // h@Wds raw
__device__ __align__(16) float dH2 [MAXN*64];   // residual out
__device__ __align__(16) float dORAW[MAXM*64];  // conv2 raw
__device__ __align__(16) float dT  [MAXB*32];   // time mlp out
__device__ float dPA[SB*128];                   // partials [block][2C]
__device__ float dPB[SB*128];
__device__ float dSC[6][64];                    // per-BN scale
__device__ float dSH[6][64];                    // per-BN shift

// ---------------- packed f32x2 helpers (sm_100a) ----------------
__device__ __forceinline__ unsigned long long ffma2(unsigned long long a,
                                                    unsigned long long b,
                                                    unsigned long long c) {
    unsigned long long d;
    asm("fma.rn.f32x2 %0, %1, %2, %3;" : "=l"(d) : "l"(a), "l"(b), "l"(c));
    return d;
}
__device__ __forceinline__ unsigned long long bcast2(float x) {
    unsigned long long d;
    unsigned int u = __float_as_uint(x);
    asm("mov.b64 %0, {%1, %1};" : "=l"(d) : "r"(u));
    return d;
}

// ---------------------------------------------------------------- time MLP
__global__ void k_time(const float* __restrict__ emb,
                       const float* __restrict__ Wt1, const float* __restrict__ bt1,
                       const float* __restrict__ Wt2, const float* __restrict__ bt2,
                       const int*   __restrict__ time, int B) {
    __shared__ float z[MAXB*32];
    int t = threadIdx.x;
    int b = t >> 5, c = t & 31;
    const float* e = emb + time[b]*32;
    float v = bt1[c];
    #pragma unroll
    for (int j = 0; j < 32; j++) v += e[j]*Wt1[j*32+c];
    v = v / (1.f + expf(-v));                  // silu
    z[b*32+c] = v;
    __syncthreads();
    float o = bt2[c];
    #pragma unroll
    for (int j = 0; j < 32; j++) o += z[b*32+j]*Wt2[j*32+c];
    dT[b*32+c] = o;
}

// ---------------------------------------------------------------- stats
__device__ __forceinline__ void stats_body(const float4* __restrict__ src,
                                           int n4, int C, float* __restrict__ part,
                                           int bid, float* sh) {
    int t = threadIdx.x;
    int gid = bid*256 + t;
    float s0=0,s1=0,s2=0,s3=0,q0=0,q1=0,q2=0,q3=0;
    for (int i = gid; i < n4; i += SB*256) {
        float4 v = src[i];
        s0+=v.x; q0+=v.x*v.x; s1+=v.y; q1+=v.y*v.y;
        s2+=v.z; q2+=v.z*v.z; s3+=v.w; q3+=v.w*v.w;
    }
    sh[t*8+0]=s0; sh[t*8+1]=s1; sh[t*8+2]=s2; sh[t*8+3]=s3;
    sh[t*8+4]=q0; sh[t*8+5]=q1; sh[t*8+6]=q2; sh[t*8+7]=q3;
    __syncthreads();
    if (t < C) {              // channel of (tt,j) is (4*tt+j)%C
        int j = t & 3, t0 = t >> 2, step = C >> 2;
        float S = 0.f, Q = 0.f;
        for (int tt = t0; tt < 256; tt += step) { S += sh[tt*8+j]; Q += sh[tt*8+4+j]; }
        part[bid*2*C + t]     = S;
        part[bid*2*C + C + t] = Q;
    }
}

__global__ void k_stats(const float4* __restrict__ src, int n4, int C,
                        float* __restrict__ part) {
    __shared__ float sh[256*8];
    stats_body(src, n4, C, part, blockIdx.x, sh);
}

// two stats in one launch: blocks [0,SB) -> src1 (C=16 -> dPA),
// blocks [SB,2SB) -> src2 (C=64 -> dPB)
__global__ void k_stats2(const float4* __restrict__ src1, int n41,
                         const float4* __restrict__ src2, int n42) {
    __shared__ float sh[256*8];
    if (blockIdx.x < SB) stats_body(src1, n41, 16, dPA, blockIdx.x, sh);
    else                 stats_body(src2, n42, 64, dPB, blockIdx.x - SB, sh);
}

// ---------------------------------------------------------------- finalize
__device__ __forceinline__ void fin_body(const float* __restrict__ part, int C,
                                         int rows, const float* __restrict__ g,
                                         const float* __restrict__ b, int slot,
                                         float* red) {
    int t = threadIdx.x, C2 = 2*C;
    if (t < C2*8) {
        int sub = t / C2, e = t - sub*C2;
        float s = 0.f;
        for (int i = sub; i < SB; i += 8) s += part[i*C2 + e];
        red[sub*C2 + e] = s;
    }
    __syncthreads();
    if (t < C) {
        float S = 0.f, SS = 0.f;
        #pragma unroll
        for (int k = 0; k < 8; k++) { S += red[k*C2 + t]; SS += red[k*C2 + C + t]; }
        float inv  = 1.f / (float)rows;
        float mean = S * inv;
        float var  = SS * inv - mean*mean;
        float sc   = g[t] * rsqrtf(var + 1e-5f);
        dSC[slot][t] = sc;
        dSH[slot][t] = b[t] - mean*sc;
    }
}

__global__ void k_fin(const float* __restrict__ part, int C, int rows,
                      const float* __restrict__ g, const float* __restrict__ b,
                      int slot) {
    __shared__ float red[8*128];
    fin_body(part, C, rows, g, b, slot, red);
}

// two finalizes in one launch: block 0 -> (dPA, C=16, slot1),
// block 1 -> (dPB, C=64, slot4)
__global__ void k_fin2(int rows,
                       const float* __restrict__ g1, const float* __restrict__ b1,
                       const float* __restrict__ g4, const float* __restrict__ b4) {
    __shared__ float red[8*128];
    if (blockIdx.x == 0) fin_body(dPA, 16, rows, g1, b1, 1, red);
    else                 fin_body(dPB, 64, rows, g4, b4, 4, red);
}

// ------------------------------------- conv k=5 (dense, packed f32x2)
#define KC0 42
__global__ void __launch_bounds__(256,3) k_conv0(const float* __restrict__ x,
                        const int* __restrict__ nb5,
                        const float* __restrict__ W0, int N) {
    __shared__ float4 sW[KC0*64];              // 42 KiB
    int row = blockIdx.x*256 + threadIdx.x;
    unsigned long long acc[16];                // 32 ch as 16 pairs
    #pragma unroll
    for (int c = 0; c < 16; c++) acc[c] = 0ull;

    for (int k0 = 0; k0 < 125; k0 += KC0) {
        int kc = min(KC0, 125 - k0);
        const float4* srcw = (const float4*)(W0 + k0*256);
        for (int i = threadIdx.x; i < kc*64; i += 256) sW[i] = srcw[i];
        __syncthreads();
        if (row < N) {
            for (int kk = 0; kk < kc; kk++) {
                int idx = nb5[(size_t)(k0+kk)*N + row];
                if (idx < N) {
                    const float4* xr = (const float4*)(x + (size_t)idx*8);
                    float4 a = xr[0], bb = xr[1];
                    float xv[8] = {a.x,a.y,a.z,a.w,bb.x,bb.y,bb.z,bb.w};
                    const ulonglong2* wk = (const ulonglong2*)(sW + kk*64);
                    #pragma unroll
                    for (int j = 0; j < 8; j++) {
                        unsigned long long xj = bcast2(xv[j]);
                        #pragma unroll
                        for (int c = 0; c < 8; c++) {
                            ulonglong2 w = wk[j*8 + c];
                            acc[c*2+0] = ffma2(xj, w.x, acc[c*2+0]);
                            acc[c*2+1] = ffma2(xj, w.y, acc[c*2+1]);
                        }
                    }
                }
            }
        }
        __syncthreads();
    }
    if (row < N) {
        ulonglong2* o = (ulonglong2*)(dH0 + (size_t)row*32);
        #pragma unroll
        for (int q = 0; q < 8; q++) {
            ulonglong2 v; v.x = acc[q*2]; v.y = acc[q*2+1];
            o[q] = v;
        }
    }
}

// ---------------------------------------------- R1 = [bnrelu(H0),T] @ Wb1
__global__ void __launch_bounds__(256) k_r1(const float* __restrict__ Wb1,
                     const int* __restrict__ bidx, int N) {
    __shared__ float4 sW[64*4];                // 64x16
    __shared__ float ssc[32], ssh[32];
    if (threadIdx.x < 256) sW[threadIdx.x] = ((const float4*)Wb1)[threadIdx.x];
    if (threadIdx.x < 32) { ssc[threadIdx.x] = dSC[0][threadIdx.x];
                            ssh[threadIdx.x] = dSH[0][threadIdx.x]; }
    __syncthreads();
    int row = blockIdx.x*256 + threadIdx.x;
    if (row >= N) return;

    unsigned long long acc[8];                 // 16 ch as 8 pairs
    #pragma unroll
    for (int c = 0; c < 8; c++) acc[c] = 0ull;

    const ulonglong2* wk2 = (const ulonglong2*)sW;
    const float4* h4 = (const float4*)(dH0 + (size_t)row*32);
    #pragma unroll
    for (int q = 0; q < 8; q++) {
        float4 vv = h4[q];
        float hv[4] = {vv.x,vv.y,vv.z,vv.w};
        #pragma unroll
        for (int u = 0; u < 4; u++) {
            int j = q*4+u;
            float hj = fmaxf(ssc[j]*hv[u] + ssh[j], 0.f);
            unsigned long long xj = bcast2(hj);
            #pragma unroll
            for (int c4 = 0; c4 < 4; c4++) {
                ulonglong2 w = wk2[j*4+c4];
                acc[c4*2+0] = ffma2(xj, w.x, acc[c4*2+0]);
                acc[c4*2+1] = ffma2(xj, w.y, acc[c4*2+1]);
            }
        }
    }
    const float4* t4 = (const float4*)(dT + (size_t)bidx[row]*32);
    #pragma unroll
    for (int q = 0; q < 8; q++) {
        float4 vv = t4[q];
        float hv[4] = {vv.x,vv.y,vv.z,vv.w};
        #pragma unroll
        for (int u = 0; u < 4; u++) {
            int j = 32 + q*4+u;
            unsigned long long xj = bcast2(hv[u]);
            #pragma unroll
            for (int c4 = 0; c4 < 4; c4++) {
                ulonglong2 w = wk2[j*4+c4];
                acc[c4*2+0] = ffma2(xj, w.x, acc[c4*2+0]);
                acc[c4*2+1] = ffma2(xj, w.y, acc[c4*2+1]);
            }
        }
    }
    ulonglong2* o = (ulonglong2*)(dR1 + (size_t)row*16);
    #pragma unroll
    for (int q = 0; q < 4; q++) {
        ulonglong2 v; v.x = acc[q*2]; v.y = acc[q*2+1];
        o[q] = v;
    }
}

// ---------------------------------------------- YDS = [bnrelu(H0),T] @ Wds
__global__ void __launch_bounds__(256,2) k_yds(const float* __restrict__ Wds,
                      const int* __restrict__ bidx, int N) {
    __shared__ float4 sW[64*16];               // 16 KiB
    __shared__ float ssc[32], ssh[32];
    for (int i = threadIdx.x; i < 64*16; i += 256) sW[i] = ((const float4*)Wds)[i];
    if (threadIdx.x < 32) { ssc[threadIdx.x] = dSC[0][threadIdx.x];
                            ssh[threadIdx.x] = dSH[0][threadIdx.x]; }
    __syncthreads();
    int row = blockIdx.x*256 + threadIdx.x;
    if (row >= N) return;

    unsigned long long acc[32];                // 64 ch as 32 pairs
    #pragma unroll
    for (int c = 0; c < 32; c++) acc[c] = 0ull;

    const ulonglong2* wk2 = (const ulonglong2*)sW;
    const float4* h4 = (const float4*)(dH0 + (size_t)row*32);
    #pragma unroll
    for (int q = 0; q < 8; q++) {
        float4 vv = h4[q];
        float hv[4] = {vv.x,vv.y,vv.z,vv.w};
        #pragma unroll
        for (int u = 0; u < 4; u++) {
            int j = q*4+u;
            float hj = fmaxf(ssc[j]*hv[u] + ssh[j], 0.f);
            unsigned long long xj = bcast2(hj);
            #pragma unroll
            for (int c4 = 0; c4 < 16; c4++) {
                ulonglong2 w = wk2[j*16+c4];
                acc[c4*2+0] = ffma2(xj, w.x, acc[c4*2+0]);
                acc[c4*2+1] = ffma2(xj, w.y, acc[c4*2+1]);
            }
        }
    }
    const float4* t4 = (const float4*)(dT + (size_t)bidx[row]*32);
    #pragma unroll
    for (int q = 0; q < 8; q++) {
        float4 vv = t4[q];
        float hv[4] = {vv.x,vv.y,vv.z,vv.w};
        #pragma unroll
        for (int u = 0; u < 4; u++) {
            int j = 32 + q*4+u;
            unsigned long long xj = bcast2(hv[u]);
            #pragma unroll
            for (int c4 = 0; c4 < 16; c4++) {
                ulonglong2 w = wk2[j*16+c4];
                acc[c4*2+0] = ffma2(xj, w.x, acc[c4*2+0]);
                acc[c4*2+1] = ffma2(xj, w.y, acc[c4*2+1]);
            }
        }
    }
    ulonglong2* o = (ulonglong2*)(dYDS + (size_t)row*64);
    #pragma unroll
    for (int q = 0; q < 16; q++) {
        ulonglong2 v; v.x = acc[q*2]; v.y = acc[q*2+1];
        o[q] = v;
    }
}

// ------------------------------------- conv k=3 (dense, packed f32x2)
__global__ void __launch_bounds__(256) k_conv3(const int* __restrict__ nb3,
                        const float* __restrict__ Wb2, int N) {
    __shared__ float4 sW[27*64];               // 27 KiB
    __shared__ float ssc[16], ssh[16];
    for (int i = threadIdx.x; i < 27*64; i += 256) sW[i] = ((const float4*)Wb2)[i];
    if (threadIdx.x < 16) { ssc[threadIdx.x] = dSC[1][threadIdx.x];
                            ssh[threadIdx.x] = dSH[1][threadIdx.x]; }
    __syncthreads();
    int row = blockIdx.x*256 + threadIdx.x;
    if (row >= N) return;

    unsigned long long acc[8];                 // 16 ch as 8 pairs
    #pragma unroll
    for (int c = 0; c < 8; c++) acc[c] = 0ull;

    for (int k = 0; k < 27; k++) {
        int idx = nb3[(size_t)k*N + row];
        if (idx < N) {
            const float4* rp = (const float4*)(dR1 + (size_t)idx*16);
            const ulonglong2* wk = (const ulonglong2*)(sW + k*64);
            #pragma unroll
            for (int q = 0; q < 4; q++) {
                float4 vv = rp[q];
                float av[4] = {vv.x,vv.y,vv.z,vv.w};
                #pragma unroll
                for (int u = 0; u < 4; u++) {
                    int j = q*4+u;
                    float aj = fmaxf(ssc[j]*av[u] + ssh[j], 0.f);
                    unsigned long long xj = bcast2(aj);
                    #pragma unroll
                    for (int c4 = 0; c4 < 4; c4++) {
                        ulonglong2 w = wk[j*4+c4];
                        acc[c4*2+0] = ffma2(xj, w.x, acc[c4*2+0]);
                        acc[c4*2+1] = ffma2(xj, w.y, acc[c4*2+1]);
                    }
                }
            }
        }
    }
    ulonglong2* o = (ulonglong2*)(dR2 + (size_t)row*16);
    #pragma unroll
    for (int q = 0; q < 4; q++) {
        ulonglong2 v; v.x = acc[q*2]; v.y = acc[q*2+1];
        o[q] = v;
    }
}

// ---------------------------------------------------- Y3 = bnrelu(R2) @ Wb3
__global__ void __launch_bounds__(256,2) k_y3(const float* __restrict__ Wb3, int N) {
    __shared__ float4 sW[16*16];               // 16x64
    __shared__ float ssc[16], ssh[16];
    if (threadIdx.x < 256) sW[threadIdx.x] = ((const float4*)Wb3)[threadIdx.x];
    if (threadIdx.x < 16) { ssc[threadIdx.x] = dSC[2][threadIdx.x];
                            ssh[threadIdx.x] = dSH[2][threadIdx.x]; }
    __syncthreads();
    int row = blockIdx.x*256 + threadIdx.x;
    if (row >= N) return;

    unsigned long long acc[32];                // 64 ch as 32 pairs
    #pragma unroll
    for (int c = 0; c < 32; c++) acc[c] = 0ull;

    const ulonglong2* wk2 = (const ulonglong2*)sW;
    const float4* rp = (const float4*)(dR2 + (size_t)row*16);
    #pragma unroll
    for (int q = 0; q < 4; q++) {
        float4 vv = rp[q];
        float av[4] = {vv.x,vv.y,vv.z,vv.w};
        #pragma unroll
        for (int u = 0; u < 4; u++) {
            int j = q*4+u;
            float aj = fmaxf(ssc[j]*av[u] + ssh[j], 0.f);
            unsigned long long xj = bcast2(aj);
            #pragma unroll
            for (int c4 = 0; c4 < 16; c4++) {
                ulonglong2 w = wk2[j*16+c4];
                acc[c4*2+0] = ffma2(xj, w.x, acc[c4*2+0]);
                acc[c4*2+1] = ffma2(xj, w.y, acc[c4*2+1]);
            }
        }
    }
    ulonglong2* o = (ulonglong2*)(dY3 + (size_t)row*64);
    #pragma unroll
    for (int q = 0; q < 16; q++) {
        ulonglong2 v; v.x = acc[q*2]; v.y = acc[q*2+1];
        o[q] = v;
    }
}

// -------------------------------------- H2 = relu(bn3(Y3) + bnds(YDS))
__global__ void k_h2(int N) {
    int i = blockIdx.x*256 + threadIdx.x;
    int total4 = N*16;
    if (i >= total4) return;
    int c0 = (i*4) & 63;
    float4 y  = ((const float4*)dY3 )[i];
    float4 yd = ((const float4*)dYDS)[i];
    float4 r;
    r.x = fmaxf(dSC[3][c0+0]*y.x + dSH[3][c0+0] + dSC[4][c0+0]*yd.x + dSH[4][c0+0], 0.f);
    r.y = fmaxf(dSC[3][c0+1]*y.y + dSH[3][c0+1] + dSC[4][c0+1]*yd.y + dSH[4][c0+1], 0.f);
    r.z = fmaxf(dSC[3][c0+2]*y.z + dSH[3][c0+2] + dSC[4][c0+2]*yd.z + dSH[4][c0+2], 0.f);
    r.w = fmaxf(dSC[3][c0+3]*y.w + dSH[3][c0+3] + dSC[4][c0+3]*yd.w + dSH[4][c0+3], 0.f);
    ((float4*)dH2)[i] = r;
}

// ------------------------------------- conv k=2 (dense, packed f32x2)
#define KC2 2
__global__ void __launch_bounds__(256,2) k_conv2(const int* __restrict__ nb2,
                        const float* __restrict__ Wd, int M, int N) {
    __shared__ float4 sW[KC2*1024];            // 32 KiB
    int row = blockIdx.x*256 + threadIdx.x;
    unsigned long long acc[32];                // 64 ch as 32 pairs
    #pragma unroll
    for (int c = 0; c < 32; c++) acc[c] = 0ull;

    for (int k0 = 0; k0 < 8; k0 += KC2) {
        const float4* srcw = (const float4*)(Wd + k0*4096);
        for (int i = threadIdx.x; i < KC2*1024; i += 256) sW[i] = srcw[i];
        __syncthreads();
        if (row < M) {
            #pragma unroll
            for (int kk = 0; kk < KC2; kk++) {
                int idx = nb2[(size_t)(k0+kk)*M + row];
                if (idx < N) {
                    const float4* hp = (const float4*)(dH2 + (size_t)idx*64);
                    const ulonglong2* wk = (const ulonglong2*)(sW + kk*1024);
                    #pragma unroll
                    for (int q = 0; q < 16; q++) {
                        float4 h4 = hp[q];
                        float hv[4] = {h4.x,h4.y,h4.z,h4.w};
                        #pragma unroll
                        for (int u = 0; u < 4; u++) {
                            int j = q*4+u;
                            unsigned long long xj = bcast2(hv[u]);
                            const ulonglong2* wj = wk + j*16;
                            #pragma unroll
                            for (int c4 = 0; c4 < 16; c4++) {
                                ulonglong2 w = wj[c4];
                                acc[c4*2+0] = ffma2(xj, w.x, acc[c4*2+0]);
                                acc[c4*2+1] = ffma2(xj, w.y, acc[c4*2+1]);
                            }
                        }
                    }
                }
            }
        }
        __syncthreads();
    }
    if (row < M) {
        ulonglong2* o = (ulonglong2*)(dORAW + (size_t)row*64);
        #pragma unroll
        for (int q = 0; q < 16; q++) {
            ulonglong2 v; v.x = acc[q*2]; v.y = acc[q*2+1];
            o[q] = v;
        }
    }
}

// ---------------------------------------------------- out = relu(bn(ORAW))
__global__ void k_apply(float* __restrict__ out, int M) {
    int i = blockIdx.x*256 + threadIdx.x;
    int total4 = M*16;
    if (i >= total4) return;
    int c0 = (i*4) & 63;
    float4 v = ((const float4*)dORAW)[i];
    float4 r;
    r.x = fmaxf(dSC[5][c0+0]*v.x + dSH[5][c0+0], 0.f);
    r.y = fmaxf(dSC[5][c0+1]*v.y + dSH[5][c0+1], 0.f);
    r.z = fmaxf(dSC[5][c0+2]*v.z + dSH[5][c0+2], 0.f);
    r.w = fmaxf(dSC[5][c0+3]*v.w + dSH[5][c0+3], 0.f);
    ((float4*)out)[i] = r;
}

// ---------------------------------------------------------------------------
extern "C" void kernel_launch(void* const* d_in, const int* in_sizes, int n_in,
                              void* d_out, int out_size) {
    const float* x      = (const float*)d_in[0];
    const float* W0     = (const float*)d_in[1];
    const float* g0     = (const float*)d_in[2];
    const float* b0     = (const float*)d_in[3];
    const float* emb    = (const float*)d_in[4];
    const float* Wt1    = (const float*)d_in[5];
    const float* bt1    = (const float*)d_in[6];
    const float* Wt2    = (const float*)d_in[7];
    const float* bt2    = (const float*)d_in[8];
    const float* Wb1    = (const float*)d_in[9];
    const float* gb1    = (const float*)d_in[10];
    const float* bb1    = (const float*)d_in[11];
    const float* Wb2    = (const float*)d_in[12];
    const float* gb2    = (const float*)d_in[13];
    const float* bb2    = (const float*)d_in[14];
    const float* Wb3    = (const float*)d_in[15];
    const float* gb3    = (const float*)d_in[16];
    const float* bb3    = (const float*)d_in[17];
    const float* Wds    = (const float*)d_in[18];
    const float* gds    = (const float*)d_in[19];
    const float* bds    = (const float*)d_in[20];
    const float* Wd     = (const float*)d_in[21];
    const float* gd     = (const float*)d_in[22];
    const float* bd     = (const float*)d_in[23];
    const int*   time   = (const int*)  d_in[24];
    const int*   bidx   = (const int*)  d_in[25];
    const int*   nb5    = (const int*)  d_in[26];
    const int*   nb3    = (const int*)  d_in[27];
    const int*   nb2    = (const int*)  d_in[28];
    float* out = (float*)d_out;

    int N = in_sizes[0] / 8;
    int B = in_sizes[24];
    int M = in_sizes[28] / 8;

    int nb = (N + 255) / 256;
    int mb = (M + 255) / 256;

    float4 *pH0, *pR1, *pR2, *pY3, *pYDS, *pOR;
    float *pA, *pB;
    cudaGetSymbolAddress((void**)&pH0, dH0);
    cudaGetSymbolAddress((void**)&pR1, dR1);
    cudaGetSymbolAddress((void**)&pR2, dR2);
    cudaGetSymbolAddress((void**)&pY3, dY3);
    cudaGetSymbolAddress((void**)&pYDS, dYDS);
    cudaGetSymbolAddress((void**)&pOR, dORAW);
    cudaGetSymbolAddress((void**)&pA, dPA);
    cudaGetSymbolAddress((void**)&pB, dPB);

    k_time<<<1, B*32>>>(emb, Wt1, bt1, Wt2, bt2, time, B);

    k_conv0<<<nb, 256>>>(x, nb5, W0, N);
    k_stats<<<SB, 256>>>(pH0, N*8, 32, pA);
    k_fin<<<1, 1024>>>(pA, 32, N, g0, b0, 0);

    k_r1 <<<nb, 256>>>(Wb1, bidx, N);
    k_yds<<<nb, 256>>>(Wds, bidx, N);
    k_stats2<<<2*SB, 256>>>(pR1, N*4, pYDS, N*16);
    k_fin2<<<2, 1024>>>(N, gb1, bb1, gds, bds);

    k_conv3<<<nb, 256>>>(nb3, Wb2, N);
    k_stats<<<SB, 256>>>(pR2, N*4, 16, pA);
    k_fin<<<1, 1024>>>(pA, 16, N, gb2, bb2, 2);

    k_y3<<<nb, 256>>>(Wb3, N);
    k_stats<<<SB, 256>>>(pY3, N*16, 64, pA);
    k_fin<<<1, 1024>>>(pA, 64, N, gb3, bb3, 3);

    k_h2<<<(N*16 + 255)/256, 256>>>(N);

    k_conv2<<<mb, 256>>>(nb2, Wd, M, N);
    k_stats<<<SB, 256>>>(pOR, M*16, 64, pA);
    k_fin<<<1, 1024>>>(pA, 64, M, gd, bd, 5);

    k_apply<<<(M*16 + 255)/256, 256>>>(out, M);
}

// round 15
// speedup vs baseline: 1.0453x; 1.0108x over previous
#include <cuda_runtime.h>
#include <math.h>

// ---------------------------------------------------------------------------
// MinkUNet block, round 15: round-12 base (595.9us) + time-MLP folded into
// the fin(slot0) launch (grid-2, same register class). conv0 plain bounds.
// ---------------------------------------------------------------------------

#define MAXN 131072
#define MAXM 131072
#define MAXB 64
#define SB   256     // stats partial blocks (fixed -> deterministic)

__device__ __align__(16) float dH0 [MAXN*32];   // conv0 raw
__device__ __align__(16) float dR1 [MAXN*16];   // h@Wb1 raw
__device__ __align__(16) float dR2 [MAXN*16];   // conv3 raw
__device__ __align__(16) float dY3 [MAXN*64];   // r@Wb3 raw
__device__ __align__(16) float dYDS[MAXN*64];   // h@Wds raw
__device__ __align__(16) float dH2 [MAXN*64];   // residual out
__device__ __align__(16) float dORAW[MAXM*64];  // conv2 raw
__device__ __align__(16) float dT  [MAXB*32];   // time mlp out
__device__ float dPA[SB*128];                   // partials [block][2C]
__device__ float dPB[SB*128];
__device__ float dSC[6][64];                    // per-BN scale
__device__ float dSH[6][64];                    // per-BN shift

// ---------------- packed f32x2 helpers (sm_100a) ----------------
__device__ __forceinline__ unsigned long long ffma2(unsigned long long a,
                                                    unsigned long long b,
                                                    unsigned long long c) {
    unsigned long long d;
    asm("fma.rn.f32x2 %0, %1, %2, %3;" : "=l"(d) : "l"(a), "l"(b), "l"(c));
    return d;
}
__device__ __forceinline__ unsigned long long bcast2(float x) {
    unsigned long long d;
    unsigned int u = __float_as_uint(x);
    asm("mov.b64 %0, {%1, %1};" : "=l"(d) : "r"(u));
    return d;
}

// ---------------------------------------------------------------- stats
__device__ __forceinline__ void stats_body(const float4* __restrict__ src,
                                           int n4, int C, float* __restrict__ part,
                                           int bid, float* sh) {
    int t = threadIdx.x;
    int gid = bid*256 + t;
    float s0=0,s1=0,s2=0,s3=0,q0=0,q1=0,q2=0,q3=0;
    for (int i = gid; i < n4; i += SB*256) {
        float4 v = src[i];
        s0+=v.x; q0+=v.x*v.x; s1+=v.y; q1+=v.y*v.y;
        s2+=v.z; q2+=v.z*v.z; s3+=v.w; q3+=v.w*v.w;
    }
    sh[t*8+0]=s0; sh[t*8+1]=s1; sh[t*8+2]=s2; sh[t*8+3]=s3;
    sh[t*8+4]=q0; sh[t*8+5]=q1; sh[t*8+6]=q2; sh[t*8+7]=q3;
    __syncthreads();
    if (t < C) {              // channel of (tt,j) is (4*tt+j)%C
        int j = t & 3, t0 = t >> 2, step = C >> 2;
        float S = 0.f, Q = 0.f;
        for (int tt = t0; tt < 256; tt += step) { S += sh[tt*8+j]; Q += sh[tt*8+4+j]; }
        part[bid*2*C + t]     = S;
        part[bid*2*C + C + t] = Q;
    }
}

__global__ void k_stats(const float4* __restrict__ src, int n4, int C,
                        float* __restrict__ part) {
    __shared__ float sh[256*8];
    stats_body(src, n4, C, part, blockIdx.x, sh);
}

// two stats in one launch: blocks [0,SB) -> src1 (C=16 -> dPA),
// blocks [SB,2SB) -> src2 (C=64 -> dPB)
__global__ void k_stats2(const float4* __restrict__ src1, int n41,
                         const float4* __restrict__ src2, int n42) {
    __shared__ float sh[256*8];
    if (blockIdx.x < SB) stats_body(src1, n41, 16, dPA, blockIdx.x, sh);
    else                 stats_body(src2, n42, 64, dPB, blockIdx.x - SB, sh);
}

// ---------------------------------------------------------------- finalize
__device__ __forceinline__ void fin_body(const float* __restrict__ part, int C,
                                         int rows, const float* __restrict__ g,
                                         const float* __restrict__ b, int slot,
                                         float* red) {
    int t = threadIdx.x, C2 = 2*C;
    if (t < C2*8) {
        int sub = t / C2, e = t - sub*C2;
        float s = 0.f;
        for (int i = sub; i < SB; i += 8) s += part[i*C2 + e];
        red[sub*C2 + e] = s;
    }
    __syncthreads();
    if (t < C) {
        float S = 0.f, SS = 0.f;
        #pragma unroll
        for (int k = 0; k < 8; k++) { S += red[k*C2 + t]; SS += red[k*C2 + C + t]; }
        float inv  = 1.f / (float)rows;
        float mean = S * inv;
        float var  = SS * inv - mean*mean;
        float sc   = g[t] * rsqrtf(var + 1e-5f);
        dSC[slot][t] = sc;
        dSH[slot][t] = b[t] - mean*sc;
    }
}

__global__ void k_fin(const float* __restrict__ part, int C, int rows,
                      const float* __restrict__ g, const float* __restrict__ b,
                      int slot) {
    __shared__ float red[8*128];
    fin_body(part, C, rows, g, b, slot, red);
}

// fin(slot0) + time-MLP in one grid-2 launch.
// block 0: finalize BN0 from dPA. block 1: 2-layer time MLP -> dT.
__global__ void k_fin_time(int rows,
                           const float* __restrict__ g0, const float* __restrict__ b0,
                           const float* __restrict__ emb,
                           const float* __restrict__ Wt1, const float* __restrict__ bt1,
                           const float* __restrict__ Wt2, const float* __restrict__ bt2,
                           const int*   __restrict__ time, int B) {
    __shared__ float buf[2048];                // fin: 8*128; time: B*32 <= 2048
    if (blockIdx.x == 0) { fin_body(dPA, 32, rows, g0, b0, 0, buf); return; }
    int t = threadIdx.x;
    int nt = B*32;
    if (t < nt) {
        int b = t >> 5, c = t & 31;
        const float* e = emb + time[b]*32;
        float v = bt1[c];
        #pragma unroll
        for (int j = 0; j < 32; j++) v += e[j]*Wt1[j*32+c];
        v = v / (1.f + expf(-v));              // silu
        buf[t] = v;
    }
    __syncthreads();
    if (t < nt) {
        int b = t >> 5, c = t & 31;
        float o = bt2[c];
        #pragma unroll
        for (int j = 0; j < 32; j++) o += buf[b*32+j]*Wt2[j*32+c];
        dT[t] = o;
    }
}

// two finalizes in one launch: block 0 -> (dPA, C=16, slot1),
// block 1 -> (dPB, C=64, slot4)
__global__ void k_fin2(int rows,
                       const float* __restrict__ g1, const float* __restrict__ b1,
                       const float* __restrict__ g4, const float* __restrict__ b4) {
    __shared__ float red[8*128];
    if (blockIdx.x == 0) fin_body(dPA, 16, rows, g1, b1, 1, red);
    else                 fin_body(dPB, 64, rows, g4, b4, 4, red);
}

// ------------------------------------- conv k=5 (dense, packed f32x2)
#define KC0 42
__global__ void __launch_bounds__(256) k_conv0(const float* __restrict__ x,
                        const int* __restrict__ nb5,
                        const float* __restrict__ W0, int N) {
    __shared__ float4 sW[KC0*64];              // 42 KiB
    int row = blockIdx.x*256 + threadIdx.x;
    unsigned long long acc[16];                // 32 ch as 16 pairs
    #pragma unroll
    for (int c = 0; c < 16; c++) acc[c] = 0ull;

    for (int k0 = 0; k0 < 125; k0 += KC0) {
        int kc = min(KC0, 125 - k0);
        const float4* srcw = (const float4*)(W0 + k0*256);
        for (int i = threadIdx.x; i < kc*64; i += 256) sW[i] = srcw[i];
        __syncthreads();
        if (row < N) {
            for (int kk = 0; kk < kc; kk++) {
                int idx = nb5[(size_t)(k0+kk)*N + row];
                if (idx < N) {
                    const float4* xr = (const float4*)(x + (size_t)idx*8);
                    float4 a = xr[0], bb = xr[1];
                    float xv[8] = {a.x,a.y,a.z,a.w,bb.x,bb.y,bb.z,bb.w};
                    const ulonglong2* wk = (const ulonglong2*)(sW + kk*64);
                    #pragma unroll
                    for (int j = 0; j < 8; j++) {
                        unsigned long long xj = bcast2(xv[j]);
                        #pragma unroll
                        for (int c = 0; c < 8; c++) {
                            ulonglong2 w = wk[j*8 + c];
                            acc[c*2+0] = ffma2(xj, w.x, acc[c*2+0]);
                            acc[c*2+1] = ffma2(xj, w.y, acc[c*2+1]);
                        }
                    }
                }
            }
        }
        __syncthreads();
    }
    if (row < N) {
        ulonglong2* o = (ulonglong2*)(dH0 + (size_t)row*32);
        #pragma unroll
        for (int q = 0; q < 8; q++) {
            ulonglong2 v; v.x = acc[q*2]; v.y = acc[q*2+1];
            o[q] = v;
        }
    }
}

// ---------------------------------------------- R1 = [bnrelu(H0),T] @ Wb1
__global__ void __launch_bounds__(256) k_r1(const float* __restrict__ Wb1,
                     const int* __restrict__ bidx, int N) {
    __shared__ float4 sW[64*4];                // 64x16
    __shared__ float ssc[32], ssh[32];
    if (threadIdx.x < 256) sW[threadIdx.x] = ((const float4*)Wb1)[threadIdx.x];
    if (threadIdx.x < 32) { ssc[threadIdx.x] = dSC[0][threadIdx.x];
                            ssh[threadIdx.x] = dSH[0][threadIdx.x]; }
    __syncthreads();
    int row = blockIdx.x*256 + threadIdx.x;
    if (row >= N) return;

    unsigned long long acc[8];                 // 16 ch as 8 pairs
    #pragma unroll
    for (int c = 0; c < 8; c++) acc[c] = 0ull;

    const ulonglong2* wk2 = (const ulonglong2*)sW;
    const float4* h4 = (const float4*)(dH0 + (size_t)row*32);
    #pragma unroll
    for (int q = 0; q < 8; q++) {
        float4 vv = h4[q];
        float hv[4] = {vv.x,vv.y,vv.z,vv.w};
        #pragma unroll
        for (int u = 0; u < 4; u++) {
            int j = q*4+u;
            float hj = fmaxf(ssc[j]*hv[u] + ssh[j], 0.f);
            unsigned long long xj = bcast2(hj);
            #pragma unroll
            for (int c4 = 0; c4 < 4; c4++) {
                ulonglong2 w = wk2[j*4+c4];
                acc[c4*2+0] = ffma2(xj, w.x, acc[c4*2+0]);
                acc[c4*2+1] = ffma2(xj, w.y, acc[c4*2+1]);
            }
        }
    }
    const float4* t4 = (const float4*)(dT + (size_t)bidx[row]*32);
    #pragma unroll
    for (int q = 0; q < 8; q++) {
        float4 vv = t4[q];
        float hv[4] = {vv.x,vv.y,vv.z,vv.w};
        #pragma unroll
        for (int u = 0; u < 4; u++) {
            int j = 32 + q*4+u;
            unsigned long long xj = bcast2(hv[u]);
            #pragma unroll
            for (int c4 = 0; c4 < 4; c4++) {
                ulonglong2 w = wk2[j*4+c4];
                acc[c4*2+0] = ffma2(xj, w.x, acc[c4*2+0]);
                acc[c4*2+1] = ffma2(xj, w.y, acc[c4*2+1]);
            }
        }
    }
    ulonglong2* o = (ulonglong2*)(dR1 + (size_t)row*16);
    #pragma unroll
    for (int q = 0; q < 4; q++) {
        ulonglong2 v; v.x = acc[q*2]; v.y = acc[q*2+1];
        o[q] = v;
    }
}

// ---------------------------------------------- YDS = [bnrelu(H0),T] @ Wds
__global__ void __launch_bounds__(256,2) k_yds(const float* __restrict__ Wds,
                      const int* __restrict__ bidx, int N) {
    __shared__ float4 sW[64*16];               // 16 KiB
    __shared__ float ssc[32], ssh[32];
    for (int i = threadIdx.x; i < 64*16; i += 256) sW[i] = ((const float4*)Wds)[i];
    if (threadIdx.x < 32) { ssc[threadIdx.x] = dSC[0][threadIdx.x];
                            ssh[threadIdx.x] = dSH[0][threadIdx.x]; }
    __syncthreads();
    int row = blockIdx.x*256 + threadIdx.x;
    if (row >= N) return;

    unsigned long long acc[32];                // 64 ch as 32 pairs
    #pragma unroll
    for (int c = 0; c < 32; c++) acc[c] = 0ull;

    const ulonglong2* wk2 = (const ulonglong2*)sW;
    const float4* h4 = (const float4*)(dH0 + (size_t)row*32);
    #pragma unroll
    for (int q = 0; q < 8; q++) {
        float4 vv = h4[q];
        float hv[4] = {vv.x,vv.y,vv.z,vv.w};
        #pragma unroll
        for (int u = 0; u < 4; u++) {
            int j = q*4+u;
            float hj = fmaxf(ssc[j]*hv[u] + ssh[j], 0.f);
            unsigned long long xj = bcast2(hj);
            #pragma unroll
            for (int c4 = 0; c4 < 16; c4++) {
                ulonglong2 w = wk2[j*16+c4];
                acc[c4*2+0] = ffma2(xj, w.x, acc[c4*2+0]);
                acc[c4*2+1] = ffma2(xj, w.y, acc[c4*2+1]);
            }
        }
    }
    const float4* t4 = (const float4*)(dT + (size_t)bidx[row]*32);
    #pragma unroll
    for (int q = 0; q < 8; q++) {
        float4 vv = t4[q];
        float hv[4] = {vv.x,vv.y,vv.z,vv.w};
        #pragma unroll
        for (int u = 0; u < 4; u++) {
            int j = 32 + q*4+u;
            unsigned long long xj = bcast2(hv[u]);
            #pragma unroll
            for (int c4 = 0; c4 < 16; c4++) {
                ulonglong2 w = wk2[j*16+c4];
                acc[c4*2+0] = ffma2(xj, w.x, acc[c4*2+0]);
                acc[c4*2+1] = ffma2(xj, w.y, acc[c4*2+1]);
            }
        }
    }
    ulonglong2* o = (ulonglong2*)(dYDS + (size_t)row*64);
    #pragma unroll
    for (int q = 0; q < 16; q++) {
        ulonglong2 v; v.x = acc[q*2]; v.y = acc[q*2+1];
        o[q] = v;
    }
}

// ------------------------------------- conv k=3 (dense, packed f32x2)
__global__ void __launch_bounds__(256) k_conv3(const int* __restrict__ nb3,
                        const float* __restrict__ Wb2, int N) {
    __shared__ float4 sW[27*64];               // 27 KiB
    __shared__ float ssc[16], ssh[16];
    for (int i = threadIdx.x; i < 27*64; i += 256) sW[i] = ((const float4*)Wb2)[i];
    if (threadIdx.x < 16) { ssc[threadIdx.x] = dSC[1][threadIdx.x];
                            ssh[threadIdx.x] = dSH[1][threadIdx.x]; }
    __syncthreads();
    int row = blockIdx.x*256 + threadIdx.x;
    if (row >= N) return;

    unsigned long long acc[8];                 // 16 ch as 8 pairs
    #pragma unroll
    for (int c = 0; c < 8; c++) acc[c] = 0ull;

    for (int k = 0; k < 27; k++) {
        int idx = nb3[(size_t)k*N + row];
        if (idx < N) {
            const float4* rp = (const float4*)(dR1 + (size_t)idx*16);
            const ulonglong2* wk = (const ulonglong2*)(sW + k*64);
            #pragma unroll
            for (int q = 0; q < 4; q++) {
                float4 vv = rp[q];
                float av[4] = {vv.x,vv.y,vv.z,vv.w};
                #pragma unroll
                for (int u = 0; u < 4; u++) {
                    int j = q*4+u;
                    float aj = fmaxf(ssc[j]*av[u] + ssh[j], 0.f);
                    unsigned long long xj = bcast2(aj);
                    #pragma unroll
                    for (int c4 = 0; c4 < 4; c4++) {
                        ulonglong2 w = wk[j*4+c4];
                        acc[c4*2+0] = ffma2(xj, w.x, acc[c4*2+0]);
                        acc[c4*2+1] = ffma2(xj, w.y, acc[c4*2+1]);
                    }
                }
            }
        }
    }
    ulonglong2* o = (ulonglong2*)(dR2 + (size_t)row*16);
    #pragma unroll
    for (int q = 0; q < 4; q++) {
        ulonglong2 v; v.x = acc[q*2]; v.y = acc[q*2+1];
        o[q] = v;
    }
}

// ---------------------------------------------------- Y3 = bnrelu(R2) @ Wb3
__global__ void __launch_bounds__(256,2) k_y3(const float* __restrict__ Wb3, int N) {
    __shared__ float4 sW[16*16];               // 16x64
    __shared__ float ssc[16], ssh[16];
    if (threadIdx.x < 256) sW[threadIdx.x] = ((const float4*)Wb3)[threadIdx.x];
    if (threadIdx.x < 16) { ssc[threadIdx.x] = dSC[2][threadIdx.x];
                            ssh[threadIdx.x] = dSH[2][threadIdx.x]; }
    __syncthreads();
    int row = blockIdx.x*256 + threadIdx.x;
    if (row >= N) return;

    unsigned long long acc[32];                // 64 ch as 32 pairs
    #pragma unroll
    for (int c = 0; c < 32; c++) acc[c] = 0ull;

    const ulonglong2* wk2 = (const ulonglong2*)sW;
    const float4* rp = (const float4*)(dR2 + (size_t)row*16);
    #pragma unroll
    for (int q = 0; q < 4; q++) {
        float4 vv = rp[q];
        float av[4] = {vv.x,vv.y,vv.z,vv.w};
        #pragma unroll
        for (int u = 0; u < 4; u++) {
            int j = q*4+u;
            float aj = fmaxf(ssc[j]*av[u] + ssh[j], 0.f);
            unsigned long long xj = bcast2(aj);
            #pragma unroll
            for (int c4 = 0; c4 < 16; c4++) {
                ulonglong2 w = wk2[j*16+c4];
                acc[c4*2+0] = ffma2(xj, w.x, acc[c4*2+0]);
                acc[c4*2+1] = ffma2(xj, w.y, acc[c4*2+1]);
            }
        }
    }
    ulonglong2* o = (ulonglong2*)(dY3 + (size_t)row*64);
    #pragma unroll
    for (int q = 0; q < 16; q++) {
        ulonglong2 v; v.x = acc[q*2]; v.y = acc[q*2+1];
        o[q] = v;
    }
}

// -------------------------------------- H2 = relu(bn3(Y3) + bnds(YDS))
__global__ void k_h2(int N) {
    int i = blockIdx.x*256 + threadIdx.x;
    int total4 = N*16;
    if (i >= total4) return;
    int c0 = (i*4) & 63;
    float4 y  = ((const float4*)dY3 )[i];
    float4 yd = ((const float4*)dYDS)[i];
    float4 r;
    r.x = fmaxf(dSC[3][c0+0]*y.x + dSH[3][c0+0] + dSC[4][c0+0]*yd.x + dSH[4][c0+0], 0.f);
    r.y = fmaxf(dSC[3][c0+1]*y.y + dSH[3][c0+1] + dSC[4][c0+1]*yd.y + dSH[4][c0+1], 0.f);
    r.z = fmaxf(dSC[3][c0+2]*y.z + dSH[3][c0+2] + dSC[4][c0+2]*yd.z + dSH[4][c0+2], 0.f);
    r.w = fmaxf(dSC[3][c0+3]*y.w + dSH[3][c0+3] + dSC[4][c0+3]*yd.w + dSH[4][c0+3], 0.f);
    ((float4*)dH2)[i] = r;
}

// ------------------------------------- conv k=2 (dense, packed f32x2)
#define KC2 2
__global__ void __launch_bounds__(256,2) k_conv2(const int* __restrict__ nb2,
                        const float* __restrict__ Wd, int M, int N) {
    __shared__ float4 sW[KC2*1024];            // 32 KiB
    int row = blockIdx.x*256 + threadIdx.x;
    unsigned long long acc[32];                // 64 ch as 32 pairs
    #pragma unroll
    for (int c = 0; c < 32; c++) acc[c] = 0ull;

    for (int k0 = 0; k0 < 8; k0 += KC2) {
        const float4* srcw = (const float4*)(Wd + k0*4096);
        for (int i = threadIdx.x; i < KC2*1024; i += 256) sW[i] = srcw[i];
        __syncthreads();
        if (row < M) {
            #pragma unroll
            for (int kk = 0; kk < KC2; kk++) {
                int idx = nb2[(size_t)(k0+kk)*M + row];
                if (idx < N) {
                    const float4* hp = (const float4*)(dH2 + (size_t)idx*64);
                    const ulonglong2* wk = (const ulonglong2*)(sW + kk*1024);
                    #pragma unroll
                    for (int q = 0; q < 16; q++) {
                        float4 h4 = hp[q];
                        float hv[4] = {h4.x,h4.y,h4.z,h4.w};
                        #pragma unroll
                        for (int u = 0; u < 4; u++) {
                            int j = q*4+u;
                            unsigned long long xj = bcast2(hv[u]);
                            const ulonglong2* wj = wk + j*16;
                            #pragma unroll
                            for (int c4 = 0; c4 < 16; c4++) {
                                ulonglong2 w = wj[c4];
                                acc[c4*2+0] = ffma2(xj, w.x, acc[c4*2+0]);
                                acc[c4*2+1] = ffma2(xj, w.y, acc[c4*2+1]);
                            }
                        }
                    }
                }
            }
        }
        __syncthreads();
    }
    if (row < M) {
        ulonglong2* o = (ulonglong2*)(dORAW + (size_t)row*64);
        #pragma unroll
        for (int q = 0; q < 16; q++) {
            ulonglong2 v; v.x = acc[q*2]; v.y = acc[q*2+1];
            o[q] = v;
        }
    }
}

// ---------------------------------------------------- out = relu(bn(ORAW))
__global__ void k_apply(float* __restrict__ out, int M) {
    int i = blockIdx.x*256 + threadIdx.x;
    int total4 = M*16;
    if (i >= total4) return;
    int c0 = (i*4) & 63;
    float4 v = ((const float4*)dORAW)[i];
    float4 r;
    r.x = fmaxf(dSC[5][c0+0]*v.x + dSH[5][c0+0], 0.f);
    r.y = fmaxf(dSC[5][c0+1]*v.y + dSH[5][c0+1], 0.f);
    r.z = fmaxf(dSC[5][c0+2]*v.z + dSH[5][c0+2], 0.f);
    r.w = fmaxf(dSC[5][c0+3]*v.w + dSH[5][c0+3], 0.f);
    ((float4*)out)[i] = r;
}

// ---------------------------------------------------------------------------
extern "C" void kernel_launch(void* const* d_in, const int* in_sizes, int n_in,
                              void* d_out, int out_size) {
    const float* x      = (const float*)d_in[0];
    const float* W0     = (const float*)d_in[1];
    const float* g0     = (const float*)d_in[2];
    const float* b0     = (const float*)d_in[3];
    const float* emb    = (const float*)d_in[4];
    const float* Wt1    = (const float*)d_in[5];
    const float* bt1    = (const float*)d_in[6];
    const float* Wt2    = (const float*)d_in[7];
    const float* bt2    = (const float*)d_in[8];
    const float* Wb1    = (const float*)d_in[9];
    const float* gb1    = (const float*)d_in[10];
    const float* bb1    = (const float*)d_in[11];
    const float* Wb2    = (const float*)d_in[12];
    const float* gb2    = (const float*)d_in[13];
    const float* bb2    = (const float*)d_in[14];
    const float* Wb3    = (const float*)d_in[15];
    const float* gb3    = (const float*)d_in[16];
    const float* bb3    = (const float*)d_in[17];
    const float* Wds    = (const float*)d_in[18];
    const float* gds    = (const float*)d_in[19];
    const float* bds    = (const float*)d_in[20];
    const float* Wd     = (const float*)d_in[21];
    const float* gd     = (const float*)d_in[22];
    const float* bd     = (const float*)d_in[23];
    const int*   time   = (const int*)  d_in[24];
    const int*   bidx   = (const int*)  d_in[25];
    const int*   nb5    = (const int*)  d_in[26];
    const int*   nb3    = (const int*)  d_in[27];
    const int*   nb2    = (const int*)  d_in[28];
    float* out = (float*)d_out;

    int N = in_sizes[0] / 8;
    int B = in_sizes[24];
    int M = in_sizes[28] / 8;

    int nb = (N + 255) / 256;
    int mb = (M + 255) / 256;

    float4 *pH0, *pR1, *pR2, *pY3, *pYDS, *pOR;
    float *pA, *pB;
    cudaGetSymbolAddress((void**)&pH0, dH0);
    cudaGetSymbolAddress((void**)&pR1, dR1);
    cudaGetSymbolAddress((void**)&pR2, dR2);
    cudaGetSymbolAddress((void**)&pY3, dY3);
    cudaGetSymbolAddress((void**)&pYDS, dYDS);
    cudaGetSymbolAddress((void**)&pOR, dORAW);
    cudaGetSymbolAddress((void**)&pA, dPA);
    cudaGetSymbolAddress((void**)&pB, dPB);

    k_conv0<<<nb, 256>>>(x, nb5, W0, N);
    k_stats<<<SB, 256>>>(pH0, N*8, 32, pA);
    k_fin_time<<<2, 1024>>>(N, g0, b0, emb, Wt1, bt1, Wt2, bt2, time, B);

    k_r1 <<<nb, 256>>>(Wb1, bidx, N);
    k_yds<<<nb, 256>>>(Wds, bidx, N);
    k_stats2<<<2*SB, 256>>>(pR1, N*4, pYDS, N*16);
    k_fin2<<<2, 1024>>>(N, gb1, bb1, gds, bds);

    k_conv3<<<nb, 256>>>(nb3, Wb2, N);
    k_stats<<<SB, 256>>>(pR2, N*4, 16, pA);
    k_fin<<<1, 1024>>>(pA, 16, N, gb2, bb2, 2);

    k_y3<<<nb, 256>>>(Wb3, N);
    k_stats<<<SB, 256>>>(pY3, N*16, 64, pA);
    k_fin<<<1, 1024>>>(pA, 64, N, gb3, bb3, 3);

    k_h2<<<(N*16 + 255)/256, 256>>>(N);

    k_conv2<<<mb, 256>>>(nb2, Wd, M, N);
    k_stats<<<SB, 256>>>(pOR, M*16, 64, pA);
    k_fin<<<1, 1024>>>(pA, 64, M, gd, bd, 5);

    k_apply<<<(M*16 + 255)/256, 256>>>(out, M);
}